// round 1
// baseline (speedup 1.0000x reference)
#include <cuda_runtime.h>
#include <math.h>

#define T_STEPS 512
#define BATCH   128
#define DIM     512
#define HID     512
#define G3      1536

#define NB  128     // persistent scan blocks (<148 SMs -> all co-resident)
#define TPB 256

// 402 MB scratch for x_proj (device-global array: allowed; no cudaMalloc)
__device__ float g_xp[(size_t)T_STEPS * BATCH * G3];
// per-step grid barrier counters (self-resetting across graph replays)
__device__ unsigned int g_bar[T_STEPS];

// ---------------------------------------------------------------------------
// Kernel 1: x_proj[m][n] = sum_k X[m][k] * W_ih[n][k] + b_ih[n]
//   M = T*B = 65536, K = 512, N = 1536
//   BM=128, BN=128, BK=16, 256 threads, 8x8 per thread (split 4+4 frags)
// ---------------------------------------------------------------------------
__global__ __launch_bounds__(256) void xproj_kernel(
    const float* __restrict__ X,
    const float* __restrict__ W,
    const float* __restrict__ bias)
{
    __shared__ float Xs[16][128];
    __shared__ float Ws[16][128];

    const int m0  = blockIdx.y * 128;
    const int n0  = blockIdx.x * 128;
    const int tid = threadIdx.x;
    const int tx  = tid & 15;     // 0..15 -> cols tx*4 and tx*4+64
    const int ty  = tid >> 4;     // 0..15 -> rows ty*4 and ty*4+64

    float acc[8][8];
#pragma unroll
    for (int i = 0; i < 8; i++)
#pragma unroll
        for (int j = 0; j < 8; j++) acc[i][j] = 0.f;

    const float* Xg = X + (size_t)m0 * DIM;
    const float* Wg = W + (size_t)n0 * DIM;

    for (int kt = 0; kt < DIM; kt += 16) {
        // stage global -> regs
        float4 xa[2], wa[2];
#pragma unroll
        for (int i = 0; i < 2; i++) {
            int idx = tid + i * 256;          // 512 float4 per tile
            int row = idx >> 2, kq = idx & 3;
            xa[i] = *(const float4*)(Xg + (size_t)row * DIM + kt + kq * 4);
            wa[i] = *(const float4*)(Wg + (size_t)row * DIM + kt + kq * 4);
        }
        __syncthreads();   // previous tile's compute done
#pragma unroll
        for (int i = 0; i < 2; i++) {
            int idx = tid + i * 256;
            int row = idx >> 2, kq = idx & 3;
            Xs[kq * 4 + 0][row] = xa[i].x;  Xs[kq * 4 + 1][row] = xa[i].y;
            Xs[kq * 4 + 2][row] = xa[i].z;  Xs[kq * 4 + 3][row] = xa[i].w;
            Ws[kq * 4 + 0][row] = wa[i].x;  Ws[kq * 4 + 1][row] = wa[i].y;
            Ws[kq * 4 + 2][row] = wa[i].z;  Ws[kq * 4 + 3][row] = wa[i].w;
        }
        __syncthreads();

#pragma unroll
        for (int k = 0; k < 16; k++) {
            float a[8], b[8];
            *(float4*)&a[0] = *(const float4*)&Xs[k][ty * 4];
            *(float4*)&a[4] = *(const float4*)&Xs[k][ty * 4 + 64];
            *(float4*)&b[0] = *(const float4*)&Ws[k][tx * 4];
            *(float4*)&b[4] = *(const float4*)&Ws[k][tx * 4 + 64];
#pragma unroll
            for (int i = 0; i < 8; i++)
#pragma unroll
                for (int j = 0; j < 8; j++)
                    acc[i][j] += a[i] * b[j];
        }
    }

    // epilogue: + bias, store to g_xp
    float4 blo = *(const float4*)(bias + n0 + tx * 4);
    float4 bhi = *(const float4*)(bias + n0 + 64 + tx * 4);
#pragma unroll
    for (int i = 0; i < 8; i++) {
        int m = m0 + ty * 4 + ((i < 4) ? i : (64 + i - 4));
        float4 v0, v1;
        v0.x = acc[i][0] + blo.x; v0.y = acc[i][1] + blo.y;
        v0.z = acc[i][2] + blo.z; v0.w = acc[i][3] + blo.w;
        v1.x = acc[i][4] + bhi.x; v1.y = acc[i][5] + bhi.y;
        v1.z = acc[i][6] + bhi.z; v1.w = acc[i][7] + bhi.w;
        *(float4*)&g_xp[(size_t)m * G3 + n0 + tx * 4]      = v0;
        *(float4*)&g_xp[(size_t)m * G3 + n0 + 64 + tx * 4] = v1;
    }
}

// ---------------------------------------------------------------------------
// Kernel 2: persistent GRU scan. 128 blocks x 256 threads.
// Block bk owns hidden cols [bk*4, bk*4+4). Its 12 W_hh rows stay in smem.
// Each step: stream full h (out[t-1]) through smem chunks, FFMA gh, gates,
// write out[t], grid barrier.
// Thread map: b = tid&127 (batch row), cg = tid>>7, cols lc0=2*cg,+1.
// ---------------------------------------------------------------------------
#define HS_STRIDE 36   // padded row stride for conflict-free float4 LDS

__global__ __launch_bounds__(256, 1) void scan_kernel(
    const float* __restrict__ Whh,
    const float* __restrict__ bhh,
    float* __restrict__ out)
{
    __shared__ float wsh[12 * 512];            // 24 KB: rows (g*4+lc)
    __shared__ float hsh[128 * HS_STRIDE];     // 18 KB: h chunk [128][32]+pad

    const int tid = threadIdx.x;
    const int bk  = blockIdx.x;
    const int c0  = bk * 4;
    const int b   = tid & 127;
    const int cg  = tid >> 7;
    const int lc0 = 2 * cg;

    // load the 12 persistent W rows: global row (g*512 + c0 + lc)
    for (int i = tid; i < 12 * 128; i += 256) {
        int row = i >> 7, kq = i & 127;
        int g = row >> 2, lc = row & 3;
        *(float4*)&wsh[row * 512 + kq * 4] =
            *(const float4*)(Whh + (size_t)(g * 512 + c0 + lc) * 512 + kq * 4);
    }
    float bh[2][3];
#pragma unroll
    for (int i = 0; i < 2; i++)
#pragma unroll
        for (int g = 0; g < 3; g++)
            bh[i][g] = bhh[g * 512 + c0 + lc0 + i];
    __syncthreads();

    for (int t = 0; t < T_STEPS; t++) {
        // --- issue epilogue loads early (hide DRAM latency behind GEMM) ---
        float xr[2], xz[2], xn[2], hpv[2];
        {
            size_t xbase = ((size_t)t * BATCH + b) * G3;
            const float* hprow = out + (size_t)(t - 1) * (BATCH * HID)
                                     + (size_t)b * HID;
#pragma unroll
            for (int i = 0; i < 2; i++) {
                int c = c0 + lc0 + i;
                xr[i] = g_xp[xbase + c];
                xz[i] = g_xp[xbase + 512 + c];
                xn[i] = g_xp[xbase + 1024 + c];
                hpv[i] = (t > 0) ? hprow[c] : 0.f;
            }
        }

        float acc[2][3];
#pragma unroll
        for (int i = 0; i < 2; i++)
#pragma unroll
            for (int g = 0; g < 3; g++) acc[i][g] = 0.f;

        if (t > 0) {
            const float* hp = out + (size_t)(t - 1) * (BATCH * HID);
            float4 pf[4];
#pragma unroll
            for (int j = 0; j < 4; j++) {             // prefetch chunk 0
                int idx = tid + j * 256;
                int row = idx >> 3, q = idx & 7;
                pf[j] = *(const float4*)(hp + (size_t)row * HID + q * 4);
            }
            for (int kc = 0; kc < 16; kc++) {
                __syncthreads();                       // smem free
#pragma unroll
                for (int j = 0; j < 4; j++) {
                    int idx = tid + j * 256;
                    int row = idx >> 3, q = idx & 7;
                    *(float4*)&hsh[row * HS_STRIDE + q * 4] = pf[j];
                }
                __syncthreads();                       // chunk visible
                if (kc < 15) {
#pragma unroll
                    for (int j = 0; j < 4; j++) {      // prefetch next chunk
                        int idx = tid + j * 256;
                        int row = idx >> 3, q = idx & 7;
                        pf[j] = *(const float4*)
                            (hp + (size_t)row * HID + (kc + 1) * 32 + q * 4);
                    }
                }
                int kg = kc * 32;
#pragma unroll
                for (int k4 = 0; k4 < 8; k4++) {
                    float4 hv = *(const float4*)&hsh[b * HS_STRIDE + k4 * 4];
#pragma unroll
                    for (int i = 0; i < 2; i++) {
#pragma unroll
                        for (int g = 0; g < 3; g++) {
                            float4 wv = *(const float4*)
                                &wsh[(g * 4 + lc0 + i) * 512 + kg + k4 * 4];
                            acc[i][g] += hv.x * wv.x + hv.y * wv.y
                                       + hv.z * wv.z + hv.w * wv.w;
                        }
                    }
                }
            }
        }

        // --- gates + write h_new ---
        {
            float* orow = out + (size_t)t * (BATCH * HID) + (size_t)b * HID;
#pragma unroll
            for (int i = 0; i < 2; i++) {
                int c = c0 + lc0 + i;
                float hr = acc[i][0] + bh[i][0];
                float hz = acc[i][1] + bh[i][1];
                float hn = acc[i][2] + bh[i][2];
                float r  = 1.f / (1.f + __expf(-(xr[i] + hr)));
                float z  = 1.f / (1.f + __expf(-(xz[i] + hz)));
                float n  = tanhf(xn[i] + r * hn);
                orow[c]  = (1.f - z) * n + z * hpv[i];
            }
        }

        // --- grid barrier (skip after last step) ---
        if (t < T_STEPS - 1) {
            __threadfence();          // release: h_new visible device-wide
            __syncthreads();
            if (tid == 0) {
                unsigned prev = atomicAdd(&g_bar[t], 1u);
                if (prev + 1u < (unsigned)NB) {
                    while (*((volatile unsigned*)(g_bar + t)) < (unsigned)NB) { }
                }
                if (bk == 0 && t > 0) g_bar[t - 1] = 0u;   // safe: all passed t-1
                __threadfence();      // acquire
            }
            __syncthreads();
        }
    }

    // final cleanup so counters are zero for the next graph replay
    __syncthreads();
    if (tid == 0) {
        __threadfence();
        unsigned d = atomicAdd(&g_bar[T_STEPS - 1], 1u);
        if (d + 1u == (unsigned)NB) {
            g_bar[T_STEPS - 2] = 0u;
            g_bar[T_STEPS - 1] = 0u;
            __threadfence();
        }
    }
}

// ---------------------------------------------------------------------------
extern "C" void kernel_launch(void* const* d_in, const int* in_sizes, int n_in,
                              void* d_out, int out_size)
{
    const float* inputs = (const float*)d_in[0];   // [T,B,D]
    const float* W_ih   = (const float*)d_in[1];   // [3H,D]
    const float* W_hh   = (const float*)d_in[2];   // [3H,H]
    const float* b_ih   = (const float*)d_in[3];   // [3H]
    const float* b_hh   = (const float*)d_in[4];   // [3H]
    float* out = (float*)d_out;                    // [T,B,H]

    (void)in_sizes; (void)n_in; (void)out_size;

    dim3 g1(G3 / 128, (T_STEPS * BATCH) / 128, 1); // 12 x 512
    xproj_kernel<<<g1, 256>>>(inputs, W_ih, b_ih);
    scan_kernel<<<NB, TPB>>>(W_hh, b_hh, out);
}

// round 2
// speedup vs baseline: 1.0003x; 1.0003x over previous
#include <cuda_runtime.h>
#include <math.h>

#define T_STEPS 512
#define BATCH   128
#define DIM     512
#define HID     512
#define G3      1536

#define NB  128     // persistent scan blocks (<148 SMs -> all co-resident)
#define TPB 256

// 402 MB scratch for x_proj (device-global array: allowed; no cudaMalloc)
__device__ float g_xp[(size_t)T_STEPS * BATCH * G3];
// per-step grid barrier counters (self-resetting across graph replays)
__device__ unsigned int g_bar[T_STEPS];

// ---------------------------------------------------------------------------
// Kernel 1: x_proj[m][n] = sum_k X[m][k] * W_ih[n][k] + b_ih[n]
//   M = T*B = 65536, K = 512, N = 1536
//   BM=128, BN=128, BK=16, 256 threads, 8x8 per thread (split 4+4 frags)
// ---------------------------------------------------------------------------
__global__ __launch_bounds__(256) void xproj_kernel(
    const float* __restrict__ X,
    const float* __restrict__ W,
    const float* __restrict__ bias)
{
    __shared__ float Xs[16][128];
    __shared__ float Ws[16][128];

    const int m0  = blockIdx.y * 128;
    const int n0  = blockIdx.x * 128;
    const int tid = threadIdx.x;
    const int tx  = tid & 15;     // 0..15 -> cols tx*4 and tx*4+64
    const int ty  = tid >> 4;     // 0..15 -> rows ty*4 and ty*4+64

    float acc[8][8];
#pragma unroll
    for (int i = 0; i < 8; i++)
#pragma unroll
        for (int j = 0; j < 8; j++) acc[i][j] = 0.f;

    const float* Xg = X + (size_t)m0 * DIM;
    const float* Wg = W + (size_t)n0 * DIM;

    for (int kt = 0; kt < DIM; kt += 16) {
        // stage global -> regs
        float4 xa[2], wa[2];
#pragma unroll
        for (int i = 0; i < 2; i++) {
            int idx = tid + i * 256;          // 512 float4 per tile
            int row = idx >> 2, kq = idx & 3;
            xa[i] = *(const float4*)(Xg + (size_t)row * DIM + kt + kq * 4);
            wa[i] = *(const float4*)(Wg + (size_t)row * DIM + kt + kq * 4);
        }
        __syncthreads();   // previous tile's compute done
#pragma unroll
        for (int i = 0; i < 2; i++) {
            int idx = tid + i * 256;
            int row = idx >> 2, kq = idx & 3;
            Xs[kq * 4 + 0][row] = xa[i].x;  Xs[kq * 4 + 1][row] = xa[i].y;
            Xs[kq * 4 + 2][row] = xa[i].z;  Xs[kq * 4 + 3][row] = xa[i].w;
            Ws[kq * 4 + 0][row] = wa[i].x;  Ws[kq * 4 + 1][row] = wa[i].y;
            Ws[kq * 4 + 2][row] = wa[i].z;  Ws[kq * 4 + 3][row] = wa[i].w;
        }
        __syncthreads();

#pragma unroll
        for (int k = 0; k < 16; k++) {
            float a[8], b[8];
            *(float4*)&a[0] = *(const float4*)&Xs[k][ty * 4];
            *(float4*)&a[4] = *(const float4*)&Xs[k][ty * 4 + 64];
            *(float4*)&b[0] = *(const float4*)&Ws[k][tx * 4];
            *(float4*)&b[4] = *(const float4*)&Ws[k][tx * 4 + 64];
#pragma unroll
            for (int i = 0; i < 8; i++)
#pragma unroll
                for (int j = 0; j < 8; j++)
                    acc[i][j] += a[i] * b[j];
        }
    }

    // epilogue: + bias, store to g_xp
    float4 blo = *(const float4*)(bias + n0 + tx * 4);
    float4 bhi = *(const float4*)(bias + n0 + 64 + tx * 4);
#pragma unroll
    for (int i = 0; i < 8; i++) {
        int m = m0 + ty * 4 + ((i < 4) ? i : (64 + i - 4));
        float4 v0, v1;
        v0.x = acc[i][0] + blo.x; v0.y = acc[i][1] + blo.y;
        v0.z = acc[i][2] + blo.z; v0.w = acc[i][3] + blo.w;
        v1.x = acc[i][4] + bhi.x; v1.y = acc[i][5] + bhi.y;
        v1.z = acc[i][6] + bhi.z; v1.w = acc[i][7] + bhi.w;
        *(float4*)&g_xp[(size_t)m * G3 + n0 + tx * 4]      = v0;
        *(float4*)&g_xp[(size_t)m * G3 + n0 + 64 + tx * 4] = v1;
    }
}

// ---------------------------------------------------------------------------
// Kernel 2: persistent GRU scan. 128 blocks x 256 threads.
// Block bk owns hidden cols [bk*4, bk*4+4). Its 12 W_hh rows stay in smem.
// Each step: stream full h (out[t-1]) through smem chunks, FFMA gh, gates,
// write out[t], grid barrier.
// Thread map: b = tid&127 (batch row), cg = tid>>7, cols lc0=2*cg,+1.
// ---------------------------------------------------------------------------
#define HS_STRIDE 36   // padded row stride for conflict-free float4 LDS

__global__ __launch_bounds__(256, 1) void scan_kernel(
    const float* __restrict__ Whh,
    const float* __restrict__ bhh,
    float* __restrict__ out)
{
    __shared__ float wsh[12 * 512];            // 24 KB: rows (g*4+lc)
    __shared__ float hsh[128 * HS_STRIDE];     // 18 KB: h chunk [128][32]+pad

    const int tid = threadIdx.x;
    const int bk  = blockIdx.x;
    const int c0  = bk * 4;
    const int b   = tid & 127;
    const int cg  = tid >> 7;
    const int lc0 = 2 * cg;

    // load the 12 persistent W rows: global row (g*512 + c0 + lc)
    for (int i = tid; i < 12 * 128; i += 256) {
        int row = i >> 7, kq = i & 127;
        int g = row >> 2, lc = row & 3;
        *(float4*)&wsh[row * 512 + kq * 4] =
            *(const float4*)(Whh + (size_t)(g * 512 + c0 + lc) * 512 + kq * 4);
    }
    float bh[2][3];
#pragma unroll
    for (int i = 0; i < 2; i++)
#pragma unroll
        for (int g = 0; g < 3; g++)
            bh[i][g] = bhh[g * 512 + c0 + lc0 + i];
    __syncthreads();

    for (int t = 0; t < T_STEPS; t++) {
        // --- issue epilogue loads early (hide DRAM latency behind GEMM) ---
        float xr[2], xz[2], xn[2], hpv[2];
        {
            size_t xbase = ((size_t)t * BATCH + b) * G3;
            const float* hprow = out + (size_t)(t - 1) * (BATCH * HID)
                                     + (size_t)b * HID;
#pragma unroll
            for (int i = 0; i < 2; i++) {
                int c = c0 + lc0 + i;
                xr[i] = g_xp[xbase + c];
                xz[i] = g_xp[xbase + 512 + c];
                xn[i] = g_xp[xbase + 1024 + c];
                hpv[i] = (t > 0) ? hprow[c] : 0.f;
            }
        }

        float acc[2][3];
#pragma unroll
        for (int i = 0; i < 2; i++)
#pragma unroll
            for (int g = 0; g < 3; g++) acc[i][g] = 0.f;

        if (t > 0) {
            const float* hp = out + (size_t)(t - 1) * (BATCH * HID);
            float4 pf[4];
#pragma unroll
            for (int j = 0; j < 4; j++) {             // prefetch chunk 0
                int idx = tid + j * 256;
                int row = idx >> 3, q = idx & 7;
                pf[j] = *(const float4*)(hp + (size_t)row * HID + q * 4);
            }
            for (int kc = 0; kc < 16; kc++) {
                __syncthreads();                       // smem free
#pragma unroll
                for (int j = 0; j < 4; j++) {
                    int idx = tid + j * 256;
                    int row = idx >> 3, q = idx & 7;
                    *(float4*)&hsh[row * HS_STRIDE + q * 4] = pf[j];
                }
                __syncthreads();                       // chunk visible
                if (kc < 15) {
#pragma unroll
                    for (int j = 0; j < 4; j++) {      // prefetch next chunk
                        int idx = tid + j * 256;
                        int row = idx >> 3, q = idx & 7;
                        pf[j] = *(const float4*)
                            (hp + (size_t)row * HID + (kc + 1) * 32 + q * 4);
                    }
                }
                int kg = kc * 32;
#pragma unroll
                for (int k4 = 0; k4 < 8; k4++) {
                    float4 hv = *(const float4*)&hsh[b * HS_STRIDE + k4 * 4];
#pragma unroll
                    for (int i = 0; i < 2; i++) {
#pragma unroll
                        for (int g = 0; g < 3; g++) {
                            float4 wv = *(const float4*)
                                &wsh[(g * 4 + lc0 + i) * 512 + kg + k4 * 4];
                            acc[i][g] += hv.x * wv.x + hv.y * wv.y
                                       + hv.z * wv.z + hv.w * wv.w;
                        }
                    }
                }
            }
        }

        // --- gates + write h_new ---
        {
            float* orow = out + (size_t)t * (BATCH * HID) + (size_t)b * HID;
#pragma unroll
            for (int i = 0; i < 2; i++) {
                int c = c0 + lc0 + i;
                float hr = acc[i][0] + bh[i][0];
                float hz = acc[i][1] + bh[i][1];
                float hn = acc[i][2] + bh[i][2];
                float r  = 1.f / (1.f + __expf(-(xr[i] + hr)));
                float z  = 1.f / (1.f + __expf(-(xz[i] + hz)));
                float n  = tanhf(xn[i] + r * hn);
                orow[c]  = (1.f - z) * n + z * hpv[i];
            }
        }

        // --- grid barrier (skip after last step) ---
        if (t < T_STEPS - 1) {
            __threadfence();          // release: h_new visible device-wide
            __syncthreads();
            if (tid == 0) {
                unsigned prev = atomicAdd(&g_bar[t], 1u);
                if (prev + 1u < (unsigned)NB) {
                    while (*((volatile unsigned*)(g_bar + t)) < (unsigned)NB) { }
                }
                if (bk == 0 && t > 0) g_bar[t - 1] = 0u;   // safe: all passed t-1
                __threadfence();      // acquire
            }
            __syncthreads();
        }
    }

    // final cleanup so counters are zero for the next graph replay
    __syncthreads();
    if (tid == 0) {
        __threadfence();
        unsigned d = atomicAdd(&g_bar[T_STEPS - 1], 1u);
        if (d + 1u == (unsigned)NB) {
            g_bar[T_STEPS - 2] = 0u;
            g_bar[T_STEPS - 1] = 0u;
            __threadfence();
        }
    }
}

// ---------------------------------------------------------------------------
extern "C" void kernel_launch(void* const* d_in, const int* in_sizes, int n_in,
                              void* d_out, int out_size)
{
    const float* inputs = (const float*)d_in[0];   // [T,B,D]
    const float* W_ih   = (const float*)d_in[1];   // [3H,D]
    const float* W_hh   = (const float*)d_in[2];   // [3H,H]
    const float* b_ih   = (const float*)d_in[3];   // [3H]
    const float* b_hh   = (const float*)d_in[4];   // [3H]
    float* out = (float*)d_out;                    // [T,B,H]

    (void)in_sizes; (void)n_in; (void)out_size;

    dim3 g1(G3 / 128, (T_STEPS * BATCH) / 128, 1); // 12 x 512
    xproj_kernel<<<g1, 256>>>(inputs, W_ih, b_ih);
    scan_kernel<<<NB, TPB>>>(W_hh, b_hh, out);
}

// round 3
// speedup vs baseline: 1.0526x; 1.0523x over previous
#include <cuda_runtime.h>
#include <math.h>

#define T_STEPS 512
#define BATCH   128
#define DIM     512
#define HID     512
#define G3      1536

#define NB  128
#define TPB 256

__device__ float g_xp[(size_t)T_STEPS * BATCH * G3];
__device__ unsigned int g_bar[T_STEPS];

// packed fp32x2 FMA: d = a*b + d (lane-wise on 2 packed floats)
__device__ __forceinline__ void ffma2(unsigned long long& d,
                                      unsigned long long a,
                                      unsigned long long b) {
    asm("fma.rn.f32x2 %0, %1, %2, %0;" : "+l"(d) : "l"(a), "l"(b));
}
__device__ __forceinline__ unsigned long long splat2(float a) {
    unsigned long long d;
    asm("mov.b64 %0, {%1, %1};" : "=l"(d) : "f"(a));
    return d;
}
__device__ __forceinline__ void unpack2(unsigned long long v, float& lo, float& hi) {
    asm("mov.b64 {%0, %1}, %2;" : "=f"(lo), "=f"(hi) : "l"(v));
}

// ---------------------------------------------------------------------------
// Kernel 1: x_proj = X @ W_ih^T + b_ih   (M=65536, K=512, N=1536)
// BM=BN=128, BK=16, 256 thr, 8x8/thread, FFMA2 packed along N
// ---------------------------------------------------------------------------
__global__ __launch_bounds__(256) void xproj_kernel(
    const float* __restrict__ X,
    const float* __restrict__ W,
    const float* __restrict__ bias)
{
    __shared__ float Xs[16][128];
    __shared__ float Ws[16][128];

    const int m0  = blockIdx.y * 128;
    const int n0  = blockIdx.x * 128;
    const int tid = threadIdx.x;
    const int tx  = tid & 15;
    const int ty  = tid >> 4;

    unsigned long long accp[8][4];
#pragma unroll
    for (int i = 0; i < 8; i++)
#pragma unroll
        for (int j = 0; j < 4; j++) accp[i][j] = 0ULL;

    const float* Xg = X + (size_t)m0 * DIM;
    const float* Wg = W + (size_t)n0 * DIM;

    for (int kt = 0; kt < DIM; kt += 16) {
        float4 xa[2], wa[2];
#pragma unroll
        for (int i = 0; i < 2; i++) {
            int idx = tid + i * 256;
            int row = idx >> 2, kq = idx & 3;
            xa[i] = *(const float4*)(Xg + (size_t)row * DIM + kt + kq * 4);
            wa[i] = *(const float4*)(Wg + (size_t)row * DIM + kt + kq * 4);
        }
        __syncthreads();
#pragma unroll
        for (int i = 0; i < 2; i++) {
            int idx = tid + i * 256;
            int row = idx >> 2, kq = idx & 3;
            Xs[kq * 4 + 0][row] = xa[i].x;  Xs[kq * 4 + 1][row] = xa[i].y;
            Xs[kq * 4 + 2][row] = xa[i].z;  Xs[kq * 4 + 3][row] = xa[i].w;
            Ws[kq * 4 + 0][row] = wa[i].x;  Ws[kq * 4 + 1][row] = wa[i].y;
            Ws[kq * 4 + 2][row] = wa[i].z;  Ws[kq * 4 + 3][row] = wa[i].w;
        }
        __syncthreads();

#pragma unroll
        for (int k = 0; k < 16; k++) {
            float a[8];
            *(float4*)&a[0] = *(const float4*)&Xs[k][ty * 4];
            *(float4*)&a[4] = *(const float4*)&Xs[k][ty * 4 + 64];
            ulonglong2 b0 = *(const ulonglong2*)&Ws[k][tx * 4];
            ulonglong2 b1 = *(const ulonglong2*)&Ws[k][tx * 4 + 64];
#pragma unroll
            for (int i = 0; i < 8; i++) {
                unsigned long long ai = splat2(a[i]);
                ffma2(accp[i][0], ai, b0.x);
                ffma2(accp[i][1], ai, b0.y);
                ffma2(accp[i][2], ai, b1.x);
                ffma2(accp[i][3], ai, b1.y);
            }
        }
    }

    float4 blo = *(const float4*)(bias + n0 + tx * 4);
    float4 bhi = *(const float4*)(bias + n0 + 64 + tx * 4);
#pragma unroll
    for (int i = 0; i < 8; i++) {
        int m = m0 + ty * 4 + ((i < 4) ? i : (64 + i - 4));
        float c[8];
        unpack2(accp[i][0], c[0], c[1]);
        unpack2(accp[i][1], c[2], c[3]);
        unpack2(accp[i][2], c[4], c[5]);
        unpack2(accp[i][3], c[6], c[7]);
        float4 v0, v1;
        v0.x = c[0] + blo.x; v0.y = c[1] + blo.y;
        v0.z = c[2] + blo.z; v0.w = c[3] + blo.w;
        v1.x = c[4] + bhi.x; v1.y = c[5] + bhi.y;
        v1.z = c[6] + bhi.z; v1.w = c[7] + bhi.w;
        *(float4*)&g_xp[(size_t)m * G3 + n0 + tx * 4]      = v0;
        *(float4*)&g_xp[(size_t)m * G3 + n0 + 64 + tx * 4] = v1;
    }
}

// ---------------------------------------------------------------------------
// Kernel 2: persistent GRU scan, FFMA2 inner product, double-buffered h chunks
// Block bk owns hidden cols [bk*4, bk*4+4). Thread: b=tid&127, 2 cols.
// ---------------------------------------------------------------------------
#define HS_STRIDE 36
#define HS_BUF (128 * HS_STRIDE)

__global__ __launch_bounds__(256, 1) void scan_kernel(
    const float* __restrict__ Whh,
    const float* __restrict__ bhh,
    float* __restrict__ out)
{
    __shared__ float wsh[12 * 512];        // 24 KB persistent W rows
    extern __shared__ float hsh[];         // 2 * 18 KB h chunk double buffer

    const int tid = threadIdx.x;
    const int bk  = blockIdx.x;
    const int c0  = bk * 4;
    const int b   = tid & 127;
    const int cg  = tid >> 7;
    const int lc0 = 2 * cg;

    for (int i = tid; i < 12 * 128; i += 256) {
        int row = i >> 7, kq = i & 127;
        int g = row >> 2, lc = row & 3;
        *(float4*)&wsh[row * 512 + kq * 4] =
            *(const float4*)(Whh + (size_t)(g * 512 + c0 + lc) * 512 + kq * 4);
    }
    float bh[2][3];
#pragma unroll
    for (int i = 0; i < 2; i++)
#pragma unroll
        for (int g = 0; g < 3; g++)
            bh[i][g] = bhh[g * 512 + c0 + lc0 + i];
    __syncthreads();

    float hprev[2] = {0.f, 0.f};           // this thread's own h[t-1] cols

    const int prow = tid >> 3;             // staging map: 32 floats per row
    const int pq   = tid & 7;

    for (int t = 0; t < T_STEPS; t++) {
        float2 xr, xz, xn;
        {
            size_t xbase = ((size_t)t * BATCH + b) * G3 + c0 + lc0;
            xr = *(const float2*)&g_xp[xbase];
            xz = *(const float2*)&g_xp[xbase + 512];
            xn = *(const float2*)&g_xp[xbase + 1024];
        }

        unsigned long long accA[2][3], accB[2][3];
#pragma unroll
        for (int i = 0; i < 2; i++)
#pragma unroll
            for (int g = 0; g < 3; g++) { accA[i][g] = 0ULL; accB[i][g] = 0ULL; }

        if (t > 0) {
            const float* hp = out + (size_t)(t - 1) * (BATCH * HID);
            float4 pf[4];
            // chunk 0 -> regs -> buf0
#pragma unroll
            for (int j = 0; j < 4; j++) {
                int idx = tid + j * 256;
                int r = idx >> 3, q = idx & 7;
                pf[j] = *(const float4*)(hp + (size_t)r * HID + q * 4);
            }
#pragma unroll
            for (int j = 0; j < 4; j++) {
                int idx = tid + j * 256;
                int r = idx >> 3, q = idx & 7;
                *(float4*)&hsh[r * HS_STRIDE + q * 4] = pf[j];
            }
            // issue chunk 1 loads
#pragma unroll
            for (int j = 0; j < 4; j++) {
                int idx = tid + j * 256;
                int r = idx >> 3, q = idx & 7;
                pf[j] = *(const float4*)(hp + (size_t)r * HID + 32 + q * 4);
            }
            __syncthreads();

            for (int kc = 0; kc < 16; kc++) {
                const int cur = kc & 1;
                if (kc < 15) {
                    // store prefetched chunk kc+1 into the other buffer
#pragma unroll
                    for (int j = 0; j < 4; j++) {
                        int idx = tid + j * 256;
                        int r = idx >> 3, q = idx & 7;
                        *(float4*)&hsh[(cur ^ 1) * HS_BUF + r * HS_STRIDE + q * 4] = pf[j];
                    }
                    if (kc < 14) {
                        // issue loads for chunk kc+2
#pragma unroll
                        for (int j = 0; j < 4; j++) {
                            int idx = tid + j * 256;
                            int r = idx >> 3, q = idx & 7;
                            pf[j] = *(const float4*)
                                (hp + (size_t)r * HID + (kc + 2) * 32 + q * 4);
                        }
                    }
                }
                const int kg = kc * 32;
                const ulonglong2* hq =
                    (const ulonglong2*)&hsh[cur * HS_BUF + b * HS_STRIDE];
#pragma unroll
                for (int k4 = 0; k4 < 8; k4++) {
                    ulonglong2 h2 = hq[k4];
#pragma unroll
                    for (int i = 0; i < 2; i++) {
#pragma unroll
                        for (int g = 0; g < 3; g++) {
                            ulonglong2 w2 = *(const ulonglong2*)
                                &wsh[(g * 4 + lc0 + i) * 512 + kg + k4 * 4];
                            ffma2(accA[i][g], h2.x, w2.x);
                            ffma2(accB[i][g], h2.y, w2.y);
                        }
                    }
                }
                __syncthreads();
            }
        }

        // gates + write h_new (2 contiguous cols -> float2 store)
        {
            float* orow = out + (size_t)t * (BATCH * HID) + (size_t)b * HID;
            float xrv[2] = {xr.x, xr.y}, xzv[2] = {xz.x, xz.y}, xnv[2] = {xn.x, xn.y};
            float2 hnew;
            float* hn2 = &hnew.x;
#pragma unroll
            for (int i = 0; i < 2; i++) {
                float la, ha, lb, hb;
                unpack2(accA[i][0], la, ha); unpack2(accB[i][0], lb, hb);
                float hr = la + ha + lb + hb + bh[i][0];
                unpack2(accA[i][1], la, ha); unpack2(accB[i][1], lb, hb);
                float hz = la + ha + lb + hb + bh[i][1];
                unpack2(accA[i][2], la, ha); unpack2(accB[i][2], lb, hb);
                float hn = la + ha + lb + hb + bh[i][2];
                float r  = 1.f / (1.f + __expf(-(xrv[i] + hr)));
                float z  = 1.f / (1.f + __expf(-(xzv[i] + hz)));
                float n  = tanhf(xnv[i] + r * hn);
                hn2[i]   = (1.f - z) * n + z * hprev[i];
                hprev[i] = hn2[i];
            }
            *(float2*)&orow[c0 + lc0] = hnew;
        }

        if (t < T_STEPS - 1) {
            __threadfence();
            __syncthreads();
            if (tid == 0) {
                unsigned prev = atomicAdd(&g_bar[t], 1u);
                if (prev + 1u < (unsigned)NB) {
                    while (*((volatile unsigned*)(g_bar + t)) < (unsigned)NB) { }
                }
                if (bk == 0 && t > 0) g_bar[t - 1] = 0u;
                __threadfence();
            }
            __syncthreads();
        }
    }

    __syncthreads();
    if (tid == 0) {
        __threadfence();
        unsigned d = atomicAdd(&g_bar[T_STEPS - 1], 1u);
        if (d + 1u == (unsigned)NB) {
            g_bar[T_STEPS - 2] = 0u;
            g_bar[T_STEPS - 1] = 0u;
            __threadfence();
        }
    }
}

// ---------------------------------------------------------------------------
extern "C" void kernel_launch(void* const* d_in, const int* in_sizes, int n_in,
                              void* d_out, int out_size)
{
    const float* inputs = (const float*)d_in[0];
    const float* W_ih   = (const float*)d_in[1];
    const float* W_hh   = (const float*)d_in[2];
    const float* b_ih   = (const float*)d_in[3];
    const float* b_hh   = (const float*)d_in[4];
    float* out = (float*)d_out;

    (void)in_sizes; (void)n_in; (void)out_size;

    static int smem_set = 0;
    const int dyn_smem = 2 * HS_BUF * (int)sizeof(float);   // ~36.9 KB
    if (!smem_set) {
        cudaFuncSetAttribute(scan_kernel,
                             cudaFuncAttributeMaxDynamicSharedMemorySize, dyn_smem);
        smem_set = 1;
    }

    dim3 g1(G3 / 128, (T_STEPS * BATCH) / 128, 1);
    xproj_kernel<<<g1, 256>>>(inputs, W_ih, b_ih);
    scan_kernel<<<NB, TPB, dyn_smem>>>(W_hh, b_hh, out);
}

// round 4
// speedup vs baseline: 1.3552x; 1.2874x over previous
#include <cuda_runtime.h>
#include <math.h>

#define T_STEPS 512
#define BATCH   128
#define DIM     512
#define HID     512
#define G3      1536

#define NB   128      // scan blocks: 4 batch-groups x 32 col-groups
#define BPG  32       // blocks per barrier group
#define STPB 128      // scan threads per block

#define WS   516      // padded smem row stride (floats): conflict-free

__device__ float g_xp[(size_t)T_STEPS * BATCH * G3];
__device__ unsigned int g_bar[4 * T_STEPS];

__device__ __forceinline__ void ffma2(unsigned long long& d,
                                      unsigned long long a,
                                      unsigned long long b) {
    asm("fma.rn.f32x2 %0, %1, %2, %0;" : "+l"(d) : "l"(a), "l"(b));
}
__device__ __forceinline__ unsigned long long splat2(float a) {
    unsigned long long d;
    asm("mov.b64 %0, {%1, %1};" : "=l"(d) : "f"(a));
    return d;
}
__device__ __forceinline__ void unpack2(unsigned long long v, float& lo, float& hi) {
    asm("mov.b64 {%0, %1}, %2;" : "=f"(lo), "=f"(hi) : "l"(v));
}

// ---------------------------------------------------------------------------
// Kernel 1: x_proj = X @ W_ih^T + b_ih   (M=65536, K=512, N=1536)
// ---------------------------------------------------------------------------
__global__ __launch_bounds__(256) void xproj_kernel(
    const float* __restrict__ X,
    const float* __restrict__ W,
    const float* __restrict__ bias)
{
    __shared__ float Xs[16][128];
    __shared__ float Ws2[16][128];

    const int m0  = blockIdx.y * 128;
    const int n0  = blockIdx.x * 128;
    const int tid = threadIdx.x;
    const int tx  = tid & 15;
    const int ty  = tid >> 4;

    unsigned long long accp[8][4];
#pragma unroll
    for (int i = 0; i < 8; i++)
#pragma unroll
        for (int j = 0; j < 4; j++) accp[i][j] = 0ULL;

    const float* Xg = X + (size_t)m0 * DIM;
    const float* Wg = W + (size_t)n0 * DIM;

    for (int kt = 0; kt < DIM; kt += 16) {
        float4 xa[2], wa[2];
#pragma unroll
        for (int i = 0; i < 2; i++) {
            int idx = tid + i * 256;
            int row = idx >> 2, kq = idx & 3;
            xa[i] = *(const float4*)(Xg + (size_t)row * DIM + kt + kq * 4);
            wa[i] = *(const float4*)(Wg + (size_t)row * DIM + kt + kq * 4);
        }
        __syncthreads();
#pragma unroll
        for (int i = 0; i < 2; i++) {
            int idx = tid + i * 256;
            int row = idx >> 2, kq = idx & 3;
            Xs[kq * 4 + 0][row] = xa[i].x;  Xs[kq * 4 + 1][row] = xa[i].y;
            Xs[kq * 4 + 2][row] = xa[i].z;  Xs[kq * 4 + 3][row] = xa[i].w;
            Ws2[kq * 4 + 0][row] = wa[i].x; Ws2[kq * 4 + 1][row] = wa[i].y;
            Ws2[kq * 4 + 2][row] = wa[i].z; Ws2[kq * 4 + 3][row] = wa[i].w;
        }
        __syncthreads();

#pragma unroll
        for (int k = 0; k < 16; k++) {
            float a[8];
            *(float4*)&a[0] = *(const float4*)&Xs[k][ty * 4];
            *(float4*)&a[4] = *(const float4*)&Xs[k][ty * 4 + 64];
            ulonglong2 b0 = *(const ulonglong2*)&Ws2[k][tx * 4];
            ulonglong2 b1 = *(const ulonglong2*)&Ws2[k][tx * 4 + 64];
#pragma unroll
            for (int i = 0; i < 8; i++) {
                unsigned long long ai = splat2(a[i]);
                ffma2(accp[i][0], ai, b0.x);
                ffma2(accp[i][1], ai, b0.y);
                ffma2(accp[i][2], ai, b1.x);
                ffma2(accp[i][3], ai, b1.y);
            }
        }
    }

    float4 blo = *(const float4*)(bias + n0 + tx * 4);
    float4 bhi = *(const float4*)(bias + n0 + 64 + tx * 4);
#pragma unroll
    for (int i = 0; i < 8; i++) {
        int m = m0 + ty * 4 + ((i < 4) ? i : (64 + i - 4));
        float c[8];
        unpack2(accp[i][0], c[0], c[1]);
        unpack2(accp[i][1], c[2], c[3]);
        unpack2(accp[i][2], c[4], c[5]);
        unpack2(accp[i][3], c[6], c[7]);
        float4 v0, v1;
        v0.x = c[0] + blo.x; v0.y = c[1] + blo.y;
        v0.z = c[2] + blo.z; v0.w = c[3] + blo.w;
        v1.x = c[4] + bhi.x; v1.y = c[5] + bhi.y;
        v1.z = c[6] + bhi.z; v1.w = c[7] + bhi.w;
        *(float4*)&g_xp[(size_t)m * G3 + n0 + tx * 4]      = v0;
        *(float4*)&g_xp[(size_t)m * G3 + n0 + 64 + tx * 4] = v1;
    }
}

// ---------------------------------------------------------------------------
// Kernel 2: persistent GRU scan.
// Grid: 128 blocks = 4 batch-groups (bg) x 32 col-groups (cg).
// Block: 128 threads. Owns batches [bg*32, +32), cols [cg*16, +16).
// Thread (bp=tid>>3, cp=tid&7): batches {2bp, 2bp+1}, cols {cp, cp+8} (local).
// Whole 32x512 h slice staged to smem each step (one sync); W_hh rows for the
// 16 cols (48 x 512) resident in smem. Barrier only among the 32 blocks of
// the same batch-group.
// ---------------------------------------------------------------------------
__global__ __launch_bounds__(STPB, 1) void scan_kernel(
    const float* __restrict__ Whh,
    const float* __restrict__ bhh,
    float* __restrict__ out)
{
    extern __shared__ float smem[];
    float* wsh = smem;                 // 48 rows x WS
    float* hsh = smem + 48 * WS;       // 32 rows x WS

    const int tid = threadIdx.x;
    const int bk  = blockIdx.x;
    const int bg  = bk >> 5;           // batch group 0..3
    const int cg  = bk & 31;           // col group  0..31
    const int bp  = tid >> 3;          // 0..15
    const int cp  = tid & 7;           // 0..7

    const int bl0 = 2 * bp;            // local batch rows
    const int bG0 = bg * 32 + bl0;     // global batch rows bG0, bG0+1
    const int cL[2] = {cp, cp + 8};    // local cols
    const int cG[2] = {cg * 16 + cp, cg * 16 + cp + 8};

    // load W_hh rows: smem row (g*16 + lc) <- global row (g*512 + cg*16 + lc)
    for (int i = tid; i < 48 * 128; i += STPB) {
        int row = i >> 7, q = i & 127;
        int g = row >> 4, lc = row & 15;
        *(float4*)&wsh[row * WS + q * 4] =
            *(const float4*)(Whh + (size_t)(g * 512 + cg * 16 + lc) * 512 + q * 4);
    }
    float bh[2][3];
#pragma unroll
    for (int c = 0; c < 2; c++)
#pragma unroll
        for (int g = 0; g < 3; g++)
            bh[c][g] = bhh[g * 512 + cG[c]];
    __syncthreads();

    float hprev[2][2] = {{0.f, 0.f}, {0.f, 0.f}};   // [b][c]

    for (int t = 0; t < T_STEPS; t++) {
        // xp gate inputs for this thread's 4 outputs (issued early)
        float xg[2][2][3];                           // [b][c][gate]
        {
#pragma unroll
            for (int i = 0; i < 2; i++) {
                const float* xb = g_xp + ((size_t)t * BATCH + bG0 + i) * G3;
#pragma unroll
                for (int c = 0; c < 2; c++)
#pragma unroll
                    for (int g = 0; g < 3; g++)
                        xg[i][c][g] = xb[g * 512 + cG[c]];
            }
        }

        unsigned long long acc[2][2][3];
#pragma unroll
        for (int i = 0; i < 2; i++)
#pragma unroll
            for (int c = 0; c < 2; c++)
#pragma unroll
                for (int g = 0; g < 3; g++) acc[i][c][g] = 0ULL;

        if (t > 0) {
            // stage the whole 32x512 h slice (coalesced, 1 float4/row/thread)
            const float* hp = out + (size_t)(t - 1) * (BATCH * HID)
                                  + (size_t)(bg * 32) * HID;
#pragma unroll 8
            for (int j = 0; j < 32; j++) {
                *(float4*)&hsh[j * WS + tid * 4] =
                    *(const float4*)(hp + (size_t)j * HID + tid * 4);
            }
            __syncthreads();

            const float* h0 = &hsh[bl0 * WS];
            const float* h1 = &hsh[(bl0 + 1) * WS];
            const float* w0r = &wsh[(0 * 16 + cL[0]) * WS];
            const float* w0z = &wsh[(1 * 16 + cL[0]) * WS];
            const float* w0n = &wsh[(2 * 16 + cL[0]) * WS];
            const float* w1r = &wsh[(0 * 16 + cL[1]) * WS];
            const float* w1z = &wsh[(1 * 16 + cL[1]) * WS];
            const float* w1n = &wsh[(2 * 16 + cL[1]) * WS];

#pragma unroll 16
            for (int k = 0; k < 512; k += 4) {
                ulonglong2 hA = *(const ulonglong2*)(h0 + k);
                ulonglong2 hB = *(const ulonglong2*)(h1 + k);
                ulonglong2 wr0 = *(const ulonglong2*)(w0r + k);
                ulonglong2 wz0 = *(const ulonglong2*)(w0z + k);
                ulonglong2 wn0 = *(const ulonglong2*)(w0n + k);
                ulonglong2 wr1 = *(const ulonglong2*)(w1r + k);
                ulonglong2 wz1 = *(const ulonglong2*)(w1z + k);
                ulonglong2 wn1 = *(const ulonglong2*)(w1n + k);

                ffma2(acc[0][0][0], hA.x, wr0.x); ffma2(acc[0][0][0], hA.y, wr0.y);
                ffma2(acc[0][0][1], hA.x, wz0.x); ffma2(acc[0][0][1], hA.y, wz0.y);
                ffma2(acc[0][0][2], hA.x, wn0.x); ffma2(acc[0][0][2], hA.y, wn0.y);
                ffma2(acc[0][1][0], hA.x, wr1.x); ffma2(acc[0][1][0], hA.y, wr1.y);
                ffma2(acc[0][1][1], hA.x, wz1.x); ffma2(acc[0][1][1], hA.y, wz1.y);
                ffma2(acc[0][1][2], hA.x, wn1.x); ffma2(acc[0][1][2], hA.y, wn1.y);
                ffma2(acc[1][0][0], hB.x, wr0.x); ffma2(acc[1][0][0], hB.y, wr0.y);
                ffma2(acc[1][0][1], hB.x, wz0.x); ffma2(acc[1][0][1], hB.y, wz0.y);
                ffma2(acc[1][0][2], hB.x, wn0.x); ffma2(acc[1][0][2], hB.y, wn0.y);
                ffma2(acc[1][1][0], hB.x, wr1.x); ffma2(acc[1][1][0], hB.y, wr1.y);
                ffma2(acc[1][1][1], hB.x, wz1.x); ffma2(acc[1][1][1], hB.y, wz1.y);
                ffma2(acc[1][1][2], hB.x, wn1.x); ffma2(acc[1][1][2], hB.y, wn1.y);
            }
            __syncthreads();     // smem free for next step's staging
        }

        // gates + write h_new
        {
            float* ob = out + (size_t)t * (BATCH * HID);
#pragma unroll
            for (int i = 0; i < 2; i++) {
                float* orow = ob + (size_t)(bG0 + i) * HID;
#pragma unroll
                for (int c = 0; c < 2; c++) {
                    float lo, hi;
                    unpack2(acc[i][c][0], lo, hi);
                    float hr = lo + hi + bh[c][0];
                    unpack2(acc[i][c][1], lo, hi);
                    float hz = lo + hi + bh[c][1];
                    unpack2(acc[i][c][2], lo, hi);
                    float hn = lo + hi + bh[c][2];
                    float r = 1.f / (1.f + __expf(-(xg[i][c][0] + hr)));
                    float z = 1.f / (1.f + __expf(-(xg[i][c][1] + hz)));
                    float n = tanhf(xg[i][c][2] + r * hn);
                    float hv = (1.f - z) * n + z * hprev[i][c];
                    hprev[i][c] = hv;
                    orow[cG[c]] = hv;
                }
            }
        }

        // group barrier (32 blocks of same batch group)
        if (t < T_STEPS - 1) {
            __threadfence();
            __syncthreads();
            if (tid == 0) {
                unsigned* ctr = &g_bar[bg * T_STEPS + t];
                unsigned prev = atomicAdd(ctr, 1u);
                if (prev + 1u < (unsigned)BPG) {
                    while (*((volatile unsigned*)ctr) < (unsigned)BPG) { }
                }
                if (cg == 0 && t > 0) g_bar[bg * T_STEPS + t - 1] = 0u;
                __threadfence();
            }
            __syncthreads();
        }
    }

    // cleanup: leave all counters zero for graph replay
    __syncthreads();
    if (tid == 0) {
        __threadfence();
        unsigned d = atomicAdd(&g_bar[bg * T_STEPS + T_STEPS - 1], 1u);
        if (d + 1u == (unsigned)BPG) {
            g_bar[bg * T_STEPS + T_STEPS - 2] = 0u;
            g_bar[bg * T_STEPS + T_STEPS - 1] = 0u;
            __threadfence();
        }
    }
}

// ---------------------------------------------------------------------------
extern "C" void kernel_launch(void* const* d_in, const int* in_sizes, int n_in,
                              void* d_out, int out_size)
{
    const float* inputs = (const float*)d_in[0];
    const float* W_ih   = (const float*)d_in[1];
    const float* W_hh   = (const float*)d_in[2];
    const float* b_ih   = (const float*)d_in[3];
    const float* b_hh   = (const float*)d_in[4];
    float* out = (float*)d_out;

    (void)in_sizes; (void)n_in; (void)out_size;

    const int dyn_smem = (48 + 32) * WS * (int)sizeof(float);   // ~165 KB
    static int smem_set = 0;
    if (!smem_set) {
        cudaFuncSetAttribute(scan_kernel,
                             cudaFuncAttributeMaxDynamicSharedMemorySize, dyn_smem);
        smem_set = 1;
    }

    dim3 g1(G3 / 128, (T_STEPS * BATCH) / 128, 1);
    xproj_kernel<<<g1, 256>>>(inputs, W_ih, b_ih);
    scan_kernel<<<NB, STPB, dyn_smem>>>(W_hh, b_hh, out);
}

// round 5
// speedup vs baseline: 1.3696x; 1.0107x over previous
#include <cuda_runtime.h>
#include <math.h>

#define T_STEPS 512
#define BATCH   128
#define DIM     512
#define HID     512
#define G3      1536

#define NB   128      // scan blocks: 4 batch-groups x 32 col-groups
#define BPG  32       // blocks per barrier group
#define STPB 256      // scan threads per block (8 warps -> 2 per SMSP)

#define WS   516      // padded smem row stride (floats): conflict-free

__device__ float g_xp[(size_t)T_STEPS * BATCH * G3];
__device__ unsigned int g_bar[4 * T_STEPS];

__device__ __forceinline__ void ffma2(unsigned long long& d,
                                      unsigned long long a,
                                      unsigned long long b) {
    asm("fma.rn.f32x2 %0, %1, %2, %0;" : "+l"(d) : "l"(a), "l"(b));
}
__device__ __forceinline__ unsigned long long splat2(float a) {
    unsigned long long d;
    asm("mov.b64 %0, {%1, %1};" : "=l"(d) : "f"(a));
    return d;
}
__device__ __forceinline__ void unpack2(unsigned long long v, float& lo, float& hi) {
    asm("mov.b64 {%0, %1}, %2;" : "=f"(lo), "=f"(hi) : "l"(v));
}

// ---------------------------------------------------------------------------
// Kernel 1: x_proj = X @ W_ih^T + b_ih   (M=65536, K=512, N=1536)
// ---------------------------------------------------------------------------
__global__ __launch_bounds__(256) void xproj_kernel(
    const float* __restrict__ X,
    const float* __restrict__ W,
    const float* __restrict__ bias)
{
    __shared__ float Xs[16][128];
    __shared__ float Ws2[16][128];

    const int m0  = blockIdx.y * 128;
    const int n0  = blockIdx.x * 128;
    const int tid = threadIdx.x;
    const int tx  = tid & 15;
    const int ty  = tid >> 4;

    unsigned long long accp[8][4];
#pragma unroll
    for (int i = 0; i < 8; i++)
#pragma unroll
        for (int j = 0; j < 4; j++) accp[i][j] = 0ULL;

    const float* Xg = X + (size_t)m0 * DIM;
    const float* Wg = W + (size_t)n0 * DIM;

    for (int kt = 0; kt < DIM; kt += 16) {
        float4 xa[2], wa[2];
#pragma unroll
        for (int i = 0; i < 2; i++) {
            int idx = tid + i * 256;
            int row = idx >> 2, kq = idx & 3;
            xa[i] = *(const float4*)(Xg + (size_t)row * DIM + kt + kq * 4);
            wa[i] = *(const float4*)(Wg + (size_t)row * DIM + kt + kq * 4);
        }
        __syncthreads();
#pragma unroll
        for (int i = 0; i < 2; i++) {
            int idx = tid + i * 256;
            int row = idx >> 2, kq = idx & 3;
            Xs[kq * 4 + 0][row] = xa[i].x;  Xs[kq * 4 + 1][row] = xa[i].y;
            Xs[kq * 4 + 2][row] = xa[i].z;  Xs[kq * 4 + 3][row] = xa[i].w;
            Ws2[kq * 4 + 0][row] = wa[i].x; Ws2[kq * 4 + 1][row] = wa[i].y;
            Ws2[kq * 4 + 2][row] = wa[i].z; Ws2[kq * 4 + 3][row] = wa[i].w;
        }
        __syncthreads();

#pragma unroll
        for (int k = 0; k < 16; k++) {
            float a[8];
            *(float4*)&a[0] = *(const float4*)&Xs[k][ty * 4];
            *(float4*)&a[4] = *(const float4*)&Xs[k][ty * 4 + 64];
            ulonglong2 b0 = *(const ulonglong2*)&Ws2[k][tx * 4];
            ulonglong2 b1 = *(const ulonglong2*)&Ws2[k][tx * 4 + 64];
#pragma unroll
            for (int i = 0; i < 8; i++) {
                unsigned long long ai = splat2(a[i]);
                ffma2(accp[i][0], ai, b0.x);
                ffma2(accp[i][1], ai, b0.y);
                ffma2(accp[i][2], ai, b1.x);
                ffma2(accp[i][3], ai, b1.y);
            }
        }
    }

    float4 blo = *(const float4*)(bias + n0 + tx * 4);
    float4 bhi = *(const float4*)(bias + n0 + 64 + tx * 4);
#pragma unroll
    for (int i = 0; i < 8; i++) {
        int m = m0 + ty * 4 + ((i < 4) ? i : (64 + i - 4));
        float c[8];
        unpack2(accp[i][0], c[0], c[1]);
        unpack2(accp[i][1], c[2], c[3]);
        unpack2(accp[i][2], c[4], c[5]);
        unpack2(accp[i][3], c[6], c[7]);
        float4 v0, v1;
        v0.x = c[0] + blo.x; v0.y = c[1] + blo.y;
        v0.z = c[2] + blo.z; v0.w = c[3] + blo.w;
        v1.x = c[4] + bhi.x; v1.y = c[5] + bhi.y;
        v1.z = c[6] + bhi.z; v1.w = c[7] + bhi.w;
        *(float4*)&g_xp[(size_t)m * G3 + n0 + tx * 4]      = v0;
        *(float4*)&g_xp[(size_t)m * G3 + n0 + 64 + tx * 4] = v1;
    }
}

// ---------------------------------------------------------------------------
// Kernel 2: persistent GRU scan, K-split across 2 warp-halves.
// Grid: 128 blocks = 4 batch-groups (bg) x 32 col-groups (cg).
// Block: 256 threads. kp = tid>>7 selects K half [kp*256, kp*256+256).
// r7 = tid&127: bp = r7>>3 (2 batches), cp = r7&7 (cols {cp, cp+8} local).
// Partial sums combined via smem; kp=0 half computes gates.
// ---------------------------------------------------------------------------
#define RED_STRIDE 13

__global__ __launch_bounds__(STPB, 1) void scan_kernel(
    const float* __restrict__ Whh,
    const float* __restrict__ bhh,
    float* __restrict__ out)
{
    extern __shared__ float smem[];
    float* wsh = smem;                         // 48 rows x WS
    float* hsh = smem + 48 * WS;               // 32 rows x WS
    float* red = smem + (48 + 32) * WS;        // 128 x RED_STRIDE

    const int tid = threadIdx.x;
    const int bk  = blockIdx.x;
    const int bg  = bk >> 5;
    const int cg  = bk & 31;
    const int kp  = tid >> 7;                  // K half
    const int r7  = tid & 127;
    const int bp  = r7 >> 3;
    const int cp  = r7 & 7;

    const int bl0 = 2 * bp;
    const int bG0 = bg * 32 + bl0;
    const int cL[2] = {cp, cp + 8};
    const int cG[2] = {cg * 16 + cp, cg * 16 + cp + 8};
    const int kofs = kp * 256;

    // load W_hh rows: smem row (g*16 + lc) <- global row (g*512 + cg*16 + lc)
    for (int i = tid; i < 48 * 128; i += STPB) {
        int row = i >> 7, q = i & 127;
        int g = row >> 4, lc = row & 15;
        *(float4*)&wsh[row * WS + q * 4] =
            *(const float4*)(Whh + (size_t)(g * 512 + cg * 16 + lc) * 512 + q * 4);
    }
    float bh[2][3];
#pragma unroll
    for (int c = 0; c < 2; c++)
#pragma unroll
        for (int g = 0; g < 3; g++)
            bh[c][g] = bhh[g * 512 + cG[c]];
    __syncthreads();

    float hprev[2][2] = {{0.f, 0.f}, {0.f, 0.f}};   // kp==0 threads only

    const int srow = tid >> 7;           // staging: 2 rows per pass
    const int scol = (tid & 127) * 4;

    const float* h0  = &hsh[bl0 * WS + kofs];
    const float* h1  = &hsh[(bl0 + 1) * WS + kofs];
    const float* w0r = &wsh[(0 * 16 + cL[0]) * WS + kofs];
    const float* w0z = &wsh[(1 * 16 + cL[0]) * WS + kofs];
    const float* w0n = &wsh[(2 * 16 + cL[0]) * WS + kofs];
    const float* w1r = &wsh[(0 * 16 + cL[1]) * WS + kofs];
    const float* w1z = &wsh[(1 * 16 + cL[1]) * WS + kofs];
    const float* w1n = &wsh[(2 * 16 + cL[1]) * WS + kofs];

    for (int t = 0; t < T_STEPS; t++) {
        // xp gate inputs (kp==0 half only), issued early
        float xg[2][2][3];
        if (kp == 0) {
#pragma unroll
            for (int i = 0; i < 2; i++) {
                const float* xb = g_xp + ((size_t)t * BATCH + bG0 + i) * G3;
#pragma unroll
                for (int c = 0; c < 2; c++)
#pragma unroll
                    for (int g = 0; g < 3; g++)
                        xg[i][c][g] = xb[g * 512 + cG[c]];
            }
        }

        unsigned long long acc[2][2][3];
#pragma unroll
        for (int i = 0; i < 2; i++)
#pragma unroll
            for (int c = 0; c < 2; c++)
#pragma unroll
                for (int g = 0; g < 3; g++) acc[i][c][g] = 0ULL;

        if (t > 0) {
            // stage the 32x512 h slice: 16 passes x 2 rows, coalesced
            const float* hp = out + (size_t)(t - 1) * (BATCH * HID)
                                  + (size_t)(bg * 32) * HID;
#pragma unroll
            for (int j = 0; j < 16; j++) {
                int row = j * 2 + srow;
                *(float4*)&hsh[row * WS + scol] =
                    *(const float4*)(hp + (size_t)row * HID + scol);
            }
            __syncthreads();

#pragma unroll 16
            for (int k = 0; k < 256; k += 4) {
                ulonglong2 hA  = *(const ulonglong2*)(h0 + k);
                ulonglong2 hB  = *(const ulonglong2*)(h1 + k);
                ulonglong2 wr0 = *(const ulonglong2*)(w0r + k);
                ulonglong2 wz0 = *(const ulonglong2*)(w0z + k);
                ulonglong2 wn0 = *(const ulonglong2*)(w0n + k);
                ulonglong2 wr1 = *(const ulonglong2*)(w1r + k);
                ulonglong2 wz1 = *(const ulonglong2*)(w1z + k);
                ulonglong2 wn1 = *(const ulonglong2*)(w1n + k);

                ffma2(acc[0][0][0], hA.x, wr0.x); ffma2(acc[0][0][0], hA.y, wr0.y);
                ffma2(acc[0][0][1], hA.x, wz0.x); ffma2(acc[0][0][1], hA.y, wz0.y);
                ffma2(acc[0][0][2], hA.x, wn0.x); ffma2(acc[0][0][2], hA.y, wn0.y);
                ffma2(acc[0][1][0], hA.x, wr1.x); ffma2(acc[0][1][0], hA.y, wr1.y);
                ffma2(acc[0][1][1], hA.x, wz1.x); ffma2(acc[0][1][1], hA.y, wz1.y);
                ffma2(acc[0][1][2], hA.x, wn1.x); ffma2(acc[0][1][2], hA.y, wn1.y);
                ffma2(acc[1][0][0], hB.x, wr0.x); ffma2(acc[1][0][0], hB.y, wr0.y);
                ffma2(acc[1][0][1], hB.x, wz0.x); ffma2(acc[1][0][1], hB.y, wz0.y);
                ffma2(acc[1][0][2], hB.x, wn0.x); ffma2(acc[1][0][2], hB.y, wn0.y);
                ffma2(acc[1][1][0], hB.x, wr1.x); ffma2(acc[1][1][0], hB.y, wr1.y);
                ffma2(acc[1][1][1], hB.x, wz1.x); ffma2(acc[1][1][1], hB.y, wz1.y);
                ffma2(acc[1][1][2], hB.x, wn1.x); ffma2(acc[1][1][2], hB.y, wn1.y);
            }

            // kp==1 half publishes its partials
            if (kp == 1) {
                float* rp = &red[r7 * RED_STRIDE];
#pragma unroll
                for (int i = 0; i < 2; i++)
#pragma unroll
                    for (int c = 0; c < 2; c++)
#pragma unroll
                        for (int g = 0; g < 3; g++) {
                            float lo, hi;
                            unpack2(acc[i][c][g], lo, hi);
                            rp[(i * 2 + c) * 3 + g] = lo + hi;
                        }
            }
        }
        __syncthreads();   // partials visible; also frees hsh for next staging

        // gates + write h_new (kp==0 half only)
        if (kp == 0) {
            float* ob = out + (size_t)t * (BATCH * HID);
            const float* rp = &red[r7 * RED_STRIDE];
#pragma unroll
            for (int i = 0; i < 2; i++) {
                float* orow = ob + (size_t)(bG0 + i) * HID;
#pragma unroll
                for (int c = 0; c < 2; c++) {
                    float s[3];
#pragma unroll
                    for (int g = 0; g < 3; g++) {
                        float lo, hi;
                        unpack2(acc[i][c][g], lo, hi);
                        s[g] = lo + hi;
                        if (t > 0) s[g] += rp[(i * 2 + c) * 3 + g];
                    }
                    float hr = s[0] + bh[c][0];
                    float hz = s[1] + bh[c][1];
                    float hn = s[2] + bh[c][2];
                    float r = 1.f / (1.f + __expf(-(xg[i][c][0] + hr)));
                    float z = 1.f / (1.f + __expf(-(xg[i][c][1] + hz)));
                    float n = tanhf(xg[i][c][2] + r * hn);
                    float hv = (1.f - z) * n + z * hprev[i][c];
                    hprev[i][c] = hv;
                    orow[cG[c]] = hv;
                }
            }
        }

        // group barrier (32 blocks of same batch group)
        if (t < T_STEPS - 1) {
            __threadfence();
            __syncthreads();
            if (tid == 0) {
                unsigned* ctr = &g_bar[bg * T_STEPS + t];
                unsigned prev = atomicAdd(ctr, 1u);
                if (prev + 1u < (unsigned)BPG) {
                    while (*((volatile unsigned*)ctr) < (unsigned)BPG) { }
                }
                if (cg == 0 && t > 0) g_bar[bg * T_STEPS + t - 1] = 0u;
                __threadfence();
            }
            __syncthreads();
        }
    }

    // cleanup: leave all counters zero for graph replay
    __syncthreads();
    if (tid == 0) {
        __threadfence();
        unsigned d = atomicAdd(&g_bar[bg * T_STEPS + T_STEPS - 1], 1u);
        if (d + 1u == (unsigned)BPG) {
            g_bar[bg * T_STEPS + T_STEPS - 2] = 0u;
            g_bar[bg * T_STEPS + T_STEPS - 1] = 0u;
            __threadfence();
        }
    }
}

// ---------------------------------------------------------------------------
extern "C" void kernel_launch(void* const* d_in, const int* in_sizes, int n_in,
                              void* d_out, int out_size)
{
    const float* inputs = (const float*)d_in[0];
    const float* W_ih   = (const float*)d_in[1];
    const float* W_hh   = (const float*)d_in[2];
    const float* b_ih   = (const float*)d_in[3];
    const float* b_hh   = (const float*)d_in[4];
    float* out = (float*)d_out;

    (void)in_sizes; (void)n_in; (void)out_size;

    const int dyn_smem =
        ((48 + 32) * WS + 128 * RED_STRIDE) * (int)sizeof(float);  // ~172 KB
    static int smem_set = 0;
    if (!smem_set) {
        cudaFuncSetAttribute(scan_kernel,
                             cudaFuncAttributeMaxDynamicSharedMemorySize, dyn_smem);
        smem_set = 1;
    }

    dim3 g1(G3 / 128, (T_STEPS * BATCH) / 128, 1);
    xproj_kernel<<<g1, 256>>>(inputs, W_ih, b_ih);
    scan_kernel<<<NB, STPB, dyn_smem>>>(W_hh, b_hh, out);
}

// round 6
// speedup vs baseline: 1.5367x; 1.1220x over previous
#include <cuda_runtime.h>
#include <math.h>

#define T_STEPS 512
#define BATCH   128
#define DIM     512
#define HID     512
#define G3      1536

#define NB   128      // scan blocks: 4 batch-groups x 32 col-groups
#define BPG  32       // blocks per barrier group
#define STPB 256

#define WS   516      // smem row stride (floats)
#define REDL 33       // reduction inner stride (32 b + 1 pad)

__device__ float g_xp[(size_t)T_STEPS * BATCH * G3];
__device__ unsigned int g_bar[4 * T_STEPS];

__device__ __forceinline__ void ffma2(unsigned long long& d,
                                      unsigned long long a,
                                      unsigned long long b) {
    asm("fma.rn.f32x2 %0, %1, %2, %0;" : "+l"(d) : "l"(a), "l"(b));
}
__device__ __forceinline__ unsigned long long splat2(float a) {
    unsigned long long d;
    asm("mov.b64 %0, {%1, %1};" : "=l"(d) : "f"(a));
    return d;
}
__device__ __forceinline__ void unpack2(unsigned long long v, float& lo, float& hi) {
    asm("mov.b64 {%0, %1}, %2;" : "=f"(lo), "=f"(hi) : "l"(v));
}

// ---------------------------------------------------------------------------
// Kernel 1: x_proj = X @ W_ih^T + b_ih   (M=65536, K=512, N=1536)  (unchanged)
// ---------------------------------------------------------------------------
__global__ __launch_bounds__(256) void xproj_kernel(
    const float* __restrict__ X,
    const float* __restrict__ W,
    const float* __restrict__ bias)
{
    __shared__ float Xs[16][128];
    __shared__ float Ws2[16][128];

    const int m0  = blockIdx.y * 128;
    const int n0  = blockIdx.x * 128;
    const int tid = threadIdx.x;
    const int tx  = tid & 15;
    const int ty  = tid >> 4;

    unsigned long long accp[8][4];
#pragma unroll
    for (int i = 0; i < 8; i++)
#pragma unroll
        for (int j = 0; j < 4; j++) accp[i][j] = 0ULL;

    const float* Xg = X + (size_t)m0 * DIM;
    const float* Wg = W + (size_t)n0 * DIM;

    for (int kt = 0; kt < DIM; kt += 16) {
        float4 xa[2], wa[2];
#pragma unroll
        for (int i = 0; i < 2; i++) {
            int idx = tid + i * 256;
            int row = idx >> 2, kq = idx & 3;
            xa[i] = *(const float4*)(Xg + (size_t)row * DIM + kt + kq * 4);
            wa[i] = *(const float4*)(Wg + (size_t)row * DIM + kt + kq * 4);
        }
        __syncthreads();
#pragma unroll
        for (int i = 0; i < 2; i++) {
            int idx = tid + i * 256;
            int row = idx >> 2, kq = idx & 3;
            Xs[kq * 4 + 0][row] = xa[i].x;  Xs[kq * 4 + 1][row] = xa[i].y;
            Xs[kq * 4 + 2][row] = xa[i].z;  Xs[kq * 4 + 3][row] = xa[i].w;
            Ws2[kq * 4 + 0][row] = wa[i].x; Ws2[kq * 4 + 1][row] = wa[i].y;
            Ws2[kq * 4 + 2][row] = wa[i].z; Ws2[kq * 4 + 3][row] = wa[i].w;
        }
        __syncthreads();

#pragma unroll
        for (int k = 0; k < 16; k++) {
            float a[8];
            *(float4*)&a[0] = *(const float4*)&Xs[k][ty * 4];
            *(float4*)&a[4] = *(const float4*)&Xs[k][ty * 4 + 64];
            ulonglong2 b0 = *(const ulonglong2*)&Ws2[k][tx * 4];
            ulonglong2 b1 = *(const ulonglong2*)&Ws2[k][tx * 4 + 64];
#pragma unroll
            for (int i = 0; i < 8; i++) {
                unsigned long long ai = splat2(a[i]);
                ffma2(accp[i][0], ai, b0.x);
                ffma2(accp[i][1], ai, b0.y);
                ffma2(accp[i][2], ai, b1.x);
                ffma2(accp[i][3], ai, b1.y);
            }
        }
    }

    float4 blo = *(const float4*)(bias + n0 + tx * 4);
    float4 bhi = *(const float4*)(bias + n0 + 64 + tx * 4);
#pragma unroll
    for (int i = 0; i < 8; i++) {
        int m = m0 + ty * 4 + ((i < 4) ? i : (64 + i - 4));
        float c[8];
        unpack2(accp[i][0], c[0], c[1]);
        unpack2(accp[i][1], c[2], c[3]);
        unpack2(accp[i][2], c[4], c[5]);
        unpack2(accp[i][3], c[6], c[7]);
        float4 v0, v1;
        v0.x = c[0] + blo.x; v0.y = c[1] + blo.y;
        v0.z = c[2] + blo.z; v0.w = c[3] + blo.w;
        v1.x = c[4] + bhi.x; v1.y = c[5] + bhi.y;
        v1.z = c[6] + bhi.z; v1.w = c[7] + bhi.w;
        *(float4*)&g_xp[(size_t)m * G3 + n0 + tx * 4]      = v0;
        *(float4*)&g_xp[(size_t)m * G3 + n0 + 64 + tx * 4] = v1;
    }
}

// ---------------------------------------------------------------------------
// Kernel 2: persistent GRU scan, B4xC4 thread tile, K-split 8.
// Grid: 128 blocks = 4 batch-groups (bg, 32 batches) x 32 col-groups (cg, 16c).
// Block: 256 threads = 8 warps; warp ks owns k-range [ks*64, +64).
// Lane: bgrp = lane>>2 (batches {bgrp+8i}), cgrp = lane&3 (cols {cgrp+4i}).
// acc: 4b x 4c x 3g packed along k (u64). 8-way K reduction via smem.
// Gate phase: thread tid -> col co=tid>>4, batches {2*(tid&15), +1}.
// ---------------------------------------------------------------------------
__global__ __launch_bounds__(STPB, 1) void scan_kernel(
    const float* __restrict__ Whh,
    const float* __restrict__ bhh,
    float* __restrict__ out)
{
    extern __shared__ float smem[];
    float* wsh = smem;                     // 48 rows x WS
    float* hsh = smem + 48 * WS;           // 32 rows x WS
    float* red = smem + 80 * WS;           // [3][16][8][REDL]

    const int tid  = threadIdx.x;
    const int bk   = blockIdx.x;
    const int bg   = bk >> 5;
    const int cg   = bk & 31;
    const int ks   = tid >> 5;             // warp = k-slice
    const int lane = tid & 31;
    const int bgrp = lane >> 2;            // 0..7
    const int cgrp = lane & 3;             // 0..3
    const int k0   = ks * 64;

    // persistent W rows: smem row (g*16 + lc) <- Whh row (g*512 + cg*16 + lc)
    for (int i = tid; i < 48 * 128; i += STPB) {
        int row = i >> 7, q = i & 127;
        int g = row >> 4, lc = row & 15;
        *(float4*)&wsh[row * WS + q * 4] =
            *(const float4*)(Whh + (size_t)(g * 512 + cg * 16 + lc) * 512 + q * 4);
    }

    // gate-phase mapping: fixed across steps (hprev lives here)
    const int co  = tid >> 4;              // 0..15 (local col)
    const int bo  = (tid & 15) * 2;        // local batches bo, bo+1
    const int cGo = cg * 16 + co;
    const int bGo = bg * 32 + bo;
    float bh[3];
#pragma unroll
    for (int g = 0; g < 3; g++) bh[g] = bhh[g * 512 + cGo];

    __syncthreads();

    float hprev[2] = {0.f, 0.f};

    const int srow = tid >> 7;             // staging rows
    const int scol = (tid & 127) * 4;

    for (int t = 0; t < T_STEPS; t++) {
        // xp gate inputs for this thread's 2 outputs (issued early)
        float xgv[2][3];
        {
            const float* xb = g_xp + ((size_t)t * BATCH + bGo) * G3 + cGo;
#pragma unroll
            for (int j = 0; j < 2; j++)
#pragma unroll
                for (int g = 0; g < 3; g++)
                    xgv[j][g] = xb[(size_t)j * G3 + g * 512];
        }

        if (t > 0) {
            // stage 32x512 h slice (coalesced)
            const float* hp = out + (size_t)(t - 1) * (BATCH * HID)
                                  + (size_t)(bg * 32) * HID;
#pragma unroll
            for (int j = 0; j < 16; j++) {
                int row = j * 2 + srow;
                *(float4*)&hsh[row * WS + scol] =
                    *(const float4*)(hp + (size_t)row * HID + scol);
            }
            __syncthreads();

            unsigned long long acc[4][4][3];
#pragma unroll
            for (int bi = 0; bi < 4; bi++)
#pragma unroll
                for (int ci = 0; ci < 4; ci++)
#pragma unroll
                    for (int g = 0; g < 3; g++) acc[bi][ci][g] = 0ULL;

#pragma unroll 2
            for (int kk = 0; kk < 64; kk += 4) {
                const int k = k0 + kk;
                ulonglong2 h2[4];
#pragma unroll
                for (int bi = 0; bi < 4; bi++)
                    h2[bi] = *(const ulonglong2*)&hsh[(bgrp + 8 * bi) * WS + k];
                ulonglong2 w2[3][4];
#pragma unroll
                for (int g = 0; g < 3; g++)
#pragma unroll
                    for (int ci = 0; ci < 4; ci++)
                        w2[g][ci] = *(const ulonglong2*)
                            &wsh[(g * 16 + cgrp + 4 * ci) * WS + k];
#pragma unroll
                for (int bi = 0; bi < 4; bi++)
#pragma unroll
                    for (int ci = 0; ci < 4; ci++)
#pragma unroll
                        for (int g = 0; g < 3; g++) {
                            ffma2(acc[bi][ci][g], h2[bi].x, w2[g][ci].x);
                            ffma2(acc[bi][ci][g], h2[bi].y, w2[g][ci].y);
                        }
            }

            // publish partials: red[g][c][ks][b]
#pragma unroll
            for (int bi = 0; bi < 4; bi++)
#pragma unroll
                for (int ci = 0; ci < 4; ci++)
#pragma unroll
                    for (int g = 0; g < 3; g++) {
                        float lo, hi;
                        unpack2(acc[bi][ci][g], lo, hi);
                        int b = bgrp + 8 * bi;
                        int c = cgrp + 4 * ci;
                        red[((g * 16 + c) * 8 + ks) * REDL + b] = lo + hi;
                    }
            __syncthreads();
        }

        // gate phase: 2 outputs per thread (col co, batches bo, bo+1)
        {
            float* ob = out + (size_t)t * (BATCH * HID);
#pragma unroll
            for (int j = 0; j < 2; j++) {
                float s[3] = {0.f, 0.f, 0.f};
                if (t > 0) {
#pragma unroll
                    for (int g = 0; g < 3; g++) {
                        float acc0 = 0.f;
#pragma unroll
                        for (int k8 = 0; k8 < 8; k8++)
                            acc0 += red[((g * 16 + co) * 8 + k8) * REDL + bo + j];
                        s[g] = acc0;
                    }
                }
                float hr = s[0] + bh[0];
                float hz = s[1] + bh[1];
                float hn = s[2] + bh[2];
                float r = 1.f / (1.f + __expf(-(xgv[j][0] + hr)));
                float z = 1.f / (1.f + __expf(-(xgv[j][1] + hz)));
                float n = tanhf(xgv[j][2] + r * hn);
                float hv = (1.f - z) * n + z * hprev[j];
                hprev[j] = hv;
                ob[(size_t)(bGo + j) * HID + cGo] = hv;
            }
        }

        // group barrier (32 blocks of same batch group)
        if (t < T_STEPS - 1) {
            __threadfence();
            __syncthreads();
            if (tid == 0) {
                unsigned* ctr = &g_bar[bg * T_STEPS + t];
                unsigned prev = atomicAdd(ctr, 1u);
                if (prev + 1u < (unsigned)BPG) {
                    while (*((volatile unsigned*)ctr) < (unsigned)BPG) { }
                }
                if (cg == 0 && t > 0) g_bar[bg * T_STEPS + t - 1] = 0u;
                __threadfence();
            }
            __syncthreads();
        }
    }

    // cleanup: leave all counters zero for graph replay
    __syncthreads();
    if (tid == 0) {
        __threadfence();
        unsigned d = atomicAdd(&g_bar[bg * T_STEPS + T_STEPS - 1], 1u);
        if (d + 1u == (unsigned)BPG) {
            g_bar[bg * T_STEPS + T_STEPS - 2] = 0u;
            g_bar[bg * T_STEPS + T_STEPS - 1] = 0u;
            __threadfence();
        }
    }
}

// ---------------------------------------------------------------------------
extern "C" void kernel_launch(void* const* d_in, const int* in_sizes, int n_in,
                              void* d_out, int out_size)
{
    const float* inputs = (const float*)d_in[0];
    const float* W_ih   = (const float*)d_in[1];
    const float* W_hh   = (const float*)d_in[2];
    const float* b_ih   = (const float*)d_in[3];
    const float* b_hh   = (const float*)d_in[4];
    float* out = (float*)d_out;

    (void)in_sizes; (void)n_in; (void)out_size;

    const int dyn_smem =
        (80 * WS + 3 * 16 * 8 * REDL) * (int)sizeof(float);   // ~211 KB
    static int smem_set = 0;
    if (!smem_set) {
        cudaFuncSetAttribute(scan_kernel,
                             cudaFuncAttributeMaxDynamicSharedMemorySize, dyn_smem);
        smem_set = 1;
    }

    dim3 g1(G3 / 128, (T_STEPS * BATCH) / 128, 1);
    xproj_kernel<<<g1, 256>>>(inputs, W_ih, b_ih);
    scan_kernel<<<NB, STPB, dyn_smem>>>(W_hh, b_hh, out);
}